// round 1
// baseline (speedup 1.0000x reference)
#include <cuda_runtime.h>
#include <math.h>
#include <float.h>

#define B 4
#define T 8
#define NF 8192
#define C 384
#define H 12
#define TOPK 32
#define D 32
#define HT (H*T)        /* 96 */
#define ROWS (T+NF)     /* 8200 */
#define SCALE 0.17677669529663687f

// ---------------- scratch (static device globals; no runtime alloc) ----------
__device__ float g_qk[B*HT*C];                    // (b, h*T+t, c)  ~590KB
__device__ float g_attn[(size_t)B*HT*NF];         // (b*HT+ht, n)   ~12.6MB
__device__ float g_w[B*HT*TOPK];
__device__ int   g_idx[B*HT*TOPK];

// ---------------- kernel 1: zero the output ----------------------------------
__global__ void zero_out_kernel(float4* __restrict__ out, int n4) {
    float4 z = make_float4(0.f, 0.f, 0.f, 0.f);
    for (int i = blockIdx.x * blockDim.x + threadIdx.x; i < n4;
         i += gridDim.x * blockDim.x)
        out[i] = z;
}

// ---------------- kernel 2: qk[b,h,t,c] = SCALE * sum_d q[bhtd]*kv_w[c,hD+d] --
// q[b,t,o] = sum_c x[b,t,c]*qs_w[t,c,o]
__global__ void qk_kernel(const float* __restrict__ x,
                          const float* __restrict__ qs_w,
                          const float* __restrict__ kv_w) {
    int b = blockIdx.y, t = blockIdx.x;
    int tid = threadIdx.x;                  // 384 threads
    __shared__ float xs[C];
    __shared__ float qs[C];
    xs[tid] = x[((size_t)b*ROWS + t)*C + tid];
    __syncthreads();

    // q[o=tid]
    float acc = 0.f;
    const float* w = qs_w + (size_t)t*C*C + tid;   // qs_w[t, c, tid]
    #pragma unroll 8
    for (int c = 0; c < C; c++) acc += xs[c] * w[(size_t)c*C];
    qs[tid] = acc;
    __syncthreads();

    // qk[c=tid] for each head
    const float* kvr = kv_w + (size_t)tid*(2*C);   // row c of kv_w
    #pragma unroll
    for (int h = 0; h < H; h++) {
        float s = 0.f;
        #pragma unroll
        for (int d = 0; d < D; d++) s += qs[h*D + d] * kvr[h*D + d];
        g_qk[(((size_t)b*H + h)*T + t)*C + tid] = s * SCALE;
    }
}

// ---------------- kernel 3: attn[b, ht, n] = qk[b,ht,:] . feature[b,n,:] -----
// Per batch: M=96(ht) x N=8192 x K=384 GEMM (both operands K-contiguous).
__global__ __launch_bounds__(256) void attn_gemm_kernel(const float* __restrict__ x) {
    int b  = blockIdx.y;
    int n0 = blockIdx.x * 128;
    int tid = threadIdx.x;
    int tx = tid & 15, ty = tid >> 4;      // 16x16 thread grid
    int kk = tid & 31, r  = tid >> 5;      // loader mapping

    __shared__ float As[32][97];           // As[k][m], pad 97 -> conflict-free
    __shared__ float Bs[32][129];          // Bs[k][n], pad 129 -> conflict-free

    const float* qk   = g_qk + (size_t)b*HT*C;
    const float* feat = x + ((size_t)b*ROWS + T)*C;

    float acc[6][8];
    #pragma unroll
    for (int i = 0; i < 6; i++)
        #pragma unroll
        for (int j = 0; j < 8; j++) acc[i][j] = 0.f;

    for (int c0 = 0; c0 < C; c0 += 32) {
        #pragma unroll
        for (int i = 0; i < 12; i++) {     // 96 rows of A
            int m = r + 8*i;
            As[kk][m] = qk[(size_t)m*C + c0 + kk];
        }
        #pragma unroll
        for (int i = 0; i < 16; i++) {     // 128 rows of B
            int n = r + 8*i;
            Bs[kk][n] = feat[(size_t)(n0 + n)*C + c0 + kk];
        }
        __syncthreads();
        #pragma unroll
        for (int k2 = 0; k2 < 32; k2++) {
            float a[6], bb[8];
            #pragma unroll
            for (int i = 0; i < 6; i++) a[i] = As[k2][ty + 16*i];
            #pragma unroll
            for (int j = 0; j < 8; j++) bb[j] = Bs[k2][tx + 16*j];
            #pragma unroll
            for (int i = 0; i < 6; i++)
                #pragma unroll
                for (int j = 0; j < 8; j++) acc[i][j] += a[i] * bb[j];
        }
        __syncthreads();
    }

    float* outp = g_attn + (size_t)b*HT*NF;
    #pragma unroll
    for (int i = 0; i < 6; i++)
        #pragma unroll
        for (int j = 0; j < 8; j++)
            outp[(size_t)(ty + 16*i)*NF + n0 + tx + 16*j] = acc[i][j];
}

// ---------------- kernel 4: exact top-32 + softmax per (b,h,t) ----------------
// JAX semantics: values sorted descending, ties broken by smaller index.
__global__ __launch_bounds__(256) void topk_kernel() {
    int row = blockIdx.x;                  // b*HT + h*T + t
    int tid = threadIdx.x;                 // 256
    __shared__ float s[NF];                // 32KB
    __shared__ float rv[256];
    __shared__ int   ri[256];
    __shared__ float outv[TOPK];
    __shared__ int   outi[TOPK];

    const float* src = g_attn + (size_t)row*NF;
    for (int i = tid; i < NF; i += 256) s[i] = src[i];
    __syncthreads();

    for (int it = 0; it < TOPK; it++) {
        float bv = -FLT_MAX; int bi = NF;
        for (int i = tid; i < NF; i += 256) {
            float v = s[i];
            if (v > bv) { bv = v; bi = i; }   // ascending i -> first max kept
        }
        rv[tid] = bv; ri[tid] = bi;
        __syncthreads();
        for (int st = 128; st > 0; st >>= 1) {
            if (tid < st) {
                float v2 = rv[tid + st]; int i2 = ri[tid + st];
                if (v2 > rv[tid] || (v2 == rv[tid] && i2 < ri[tid])) {
                    rv[tid] = v2; ri[tid] = i2;
                }
            }
            __syncthreads();
        }
        if (tid == 0) {
            outv[it] = rv[0]; outi[it] = ri[0];
            s[ri[0]] = -FLT_MAX;
        }
        __syncthreads();
    }

    if (tid < 32) {
        float e = expf(outv[tid] - outv[0]);   // outv[0] is the max
        float sum = e;
        #pragma unroll
        for (int o = 16; o > 0; o >>= 1) sum += __shfl_xor_sync(0xffffffffu, sum, o);
        g_w[row*TOPK + tid]   = e / sum;
        g_idx[row*TOPK + tid] = outi[tid];
    }
}

// ---------------- kernel 5: attn_token + token_out per (b,t) ------------------
// fbar[h,c] = sum_k w*feature[idx,c];  at[h*D+d] = sum_c fbar[h,c]*kv_w[c, C+hD+d]
// out[b,t,o] = sum_c at[c]*experts_w[t,c,o]
__global__ __launch_bounds__(384) void token_kernel(const float* __restrict__ x,
                                                    const float* __restrict__ kv_w,
                                                    const float* __restrict__ experts_w,
                                                    float* __restrict__ out) {
    int b = blockIdx.y, t = blockIdx.x;
    int tid = threadIdx.x;                 // 384
    __shared__ float wsh[H][TOPK];
    __shared__ int   ish[H][TOPK];
    __shared__ float fb[H][C];             // 18KB
    __shared__ float at[C];

    {
        int h = tid >> 5, k = tid & 31;    // 12*32 == 384 exactly
        int row = (b*H + h)*T + t;
        wsh[h][k] = g_w[row*TOPK + k];
        ish[h][k] = g_idx[row*TOPK + k];
    }
    __syncthreads();

    const float* feat = x + ((size_t)b*ROWS + T)*C;
    int c = tid;
    float accl[H];
    #pragma unroll
    for (int h = 0; h < H; h++) accl[h] = 0.f;
    #pragma unroll
    for (int h = 0; h < H; h++)
        for (int k = 0; k < TOPK; k++)
            accl[h] += wsh[h][k] * feat[(size_t)ish[h][k]*C + c];
    #pragma unroll
    for (int h = 0; h < H; h++) fb[h][c] = accl[h];
    __syncthreads();

    {
        int h2 = tid >> 5, d = tid & 31;
        float s = 0.f;
        const float* col = kv_w + C + h2*D + d;     // v-half column
        #pragma unroll 8
        for (int c2 = 0; c2 < C; c2++) s += fb[h2][c2] * col[(size_t)c2*(2*C)];
        at[h2*D + d] = s;
    }
    __syncthreads();

    {
        float o_acc = 0.f;
        const float* ew = experts_w + (size_t)t*C*C + tid;
        #pragma unroll 8
        for (int c2 = 0; c2 < C; c2++) o_acc += at[c2] * ew[(size_t)c2*C];
        out[((size_t)b*ROWS + t)*C + tid] = o_acc;
    }
}

// ---------------- kernel 6: sparse feature_out scatter ------------------------
// For each (b,h,t,k): out[b, T+idx, :] += w * (feature[idx, hD:hD+D] @ ew[t, hD:hD+D, :])
__global__ __launch_bounds__(384) void scatter_kernel(const float* __restrict__ x,
                                                      const float* __restrict__ experts_w,
                                                      float* __restrict__ out) {
    int t = blockIdx.x, h = blockIdx.y, b = blockIdx.z;
    int tid = threadIdx.x;                 // 384
    __shared__ float wsh[TOPK];
    __shared__ int   ish[TOPK];
    __shared__ float fsh[TOPK][D];

    int row = (b*H + h)*T + t;
    if (tid < TOPK) {
        wsh[tid] = g_w[row*TOPK + tid];
        ish[tid] = g_idx[row*TOPK + tid];
    }
    __syncthreads();

    const float* feat = x + ((size_t)b*ROWS + T)*C;
    for (int e = tid; e < TOPK*D; e += 384) {
        int k = e >> 5, d = e & 31;
        fsh[k][d] = feat[(size_t)ish[k]*C + h*D + d] * wsh[k];
    }
    __syncthreads();

    int o = tid;
    float ecol[D];
    const float* ew = experts_w + ((size_t)t*C + h*D)*C + o;
    #pragma unroll
    for (int d = 0; d < D; d++) ecol[d] = ew[(size_t)d*C];

    float* outb = out + ((size_t)b*ROWS + T)*C;
    for (int k = 0; k < TOPK; k++) {
        float s = 0.f;
        #pragma unroll
        for (int d = 0; d < D; d++) s += fsh[k][d] * ecol[d];
        atomicAdd(&outb[(size_t)ish[k]*C + o], s);
    }
}

// ---------------- launcher ----------------------------------------------------
extern "C" void kernel_launch(void* const* d_in, const int* in_sizes, int n_in,
                              void* d_out, int out_size) {
    // Resolve inputs by element count (robust to metadata ordering):
    // x = 4*8200*384 = 12,595,200 ; kv_w = 384*768 = 294,912 ;
    // qs_w / experts_w both 8*384*384 = 1,179,648 (taken in order).
    const float* x = nullptr; const float* qs_w = nullptr;
    const float* kv_w = nullptr; const float* experts_w = nullptr;
    for (int i = 0; i < n_in; i++) {
        if (in_sizes[i] == B*ROWS*C)      x = (const float*)d_in[i];
        else if (in_sizes[i] == C*2*C)    kv_w = (const float*)d_in[i];
        else if (in_sizes[i] == T*C*C) {
            if (!qs_w) qs_w = (const float*)d_in[i];
            else       experts_w = (const float*)d_in[i];
        }
    }
    float* out = (float*)d_out;

    zero_out_kernel<<<1024, 256>>>((float4*)d_out, out_size / 4);
    qk_kernel<<<dim3(T, B), 384>>>(x, qs_w, kv_w);
    attn_gemm_kernel<<<dim3(NF/128, B), 256>>>(x);
    topk_kernel<<<B*HT, 256>>>();
    token_kernel<<<dim3(T, B), 384>>>(x, kv_w, experts_w, out);
    scatter_kernel<<<dim3(T, H, B), 384>>>(x, experts_w, out);
}

// round 2
// speedup vs baseline: 1.3917x; 1.3917x over previous
#include <cuda_runtime.h>
#include <math.h>
#include <float.h>

#define B 4
#define T 8
#define NF 8192
#define C 384
#define H 12
#define TOPK 32
#define D 32
#define HT (H*T)        /* 96 */
#define ROWS (T+NF)     /* 8200 */
#define SCALE 0.17677669529663687f

// ---------------- scratch (static device globals; no runtime alloc) ----------
__device__ float g_q[B*T*C];
__device__ float g_qk[B*HT*C];
__device__ float g_attn[(size_t)B*HT*NF];         // ~12.6MB
__device__ float g_w[B*HT*TOPK];
__device__ int   g_idx[B*HT*TOPK];
__device__ float g_fb[B*T*H*C];

// ---------------- f32x2 helpers (Blackwell packed FFMA) ----------------------
__device__ __forceinline__ unsigned long long pack2(float lo, float hi) {
    unsigned long long r;
    asm("mov.b64 %0, {%1, %2};" : "=l"(r) : "f"(lo), "f"(hi));
    return r;
}
__device__ __forceinline__ void unpack2(unsigned long long v, float& lo, float& hi) {
    asm("mov.b64 {%0, %1}, %2;" : "=f"(lo), "=f"(hi) : "l"(v));
}
__device__ __forceinline__ void fma2(unsigned long long& d,
                                     unsigned long long a, unsigned long long b) {
    asm("fma.rn.f32x2 %0, %1, %2, %0;" : "+l"(d) : "l"(a), "l"(b));
}

// ---------------- kernel 1: zero the output ----------------------------------
__global__ void zero_out_kernel(float4* __restrict__ out, int n4) {
    float4 z = make_float4(0.f, 0.f, 0.f, 0.f);
    for (int i = blockIdx.x * blockDim.x + threadIdx.x; i < n4;
         i += gridDim.x * blockDim.x)
        out[i] = z;
}

// ---------------- kernel 2a: q[b,t,o] = sum_c x[b,t,c]*qs_w[t,c,o] -----------
__global__ __launch_bounds__(128) void q_kernel(const float* __restrict__ x,
                                                const float* __restrict__ qs_w) {
    int b = blockIdx.z, t = blockIdx.y;
    int o = blockIdx.x * 128 + threadIdx.x;
    __shared__ float xs[C];
    for (int i = threadIdx.x; i < C; i += 128)
        xs[i] = x[((size_t)b*ROWS + t)*C + i];
    __syncthreads();
    float acc = 0.f;
    const float* w = qs_w + (size_t)t*C*C + o;
    #pragma unroll 16
    for (int c = 0; c < C; c++) acc += xs[c] * w[(size_t)c*C];
    g_q[((size_t)b*T + t)*C + o] = acc;
}

// ---------------- kernel 2b: qk[b,h,t,c] = SCALE * sum_d q[hD+d]*kv_w[c,hD+d]-
__global__ __launch_bounds__(384) void qk_kernel(const float* __restrict__ kv_w) {
    int b = blockIdx.y, t = blockIdx.x;
    int tid = threadIdx.x;                 // 384 = c
    __shared__ float qs[C];
    qs[tid] = g_q[((size_t)b*T + t)*C + tid];
    __syncthreads();
    const float4* kvr = (const float4*)(kv_w + (size_t)tid*(2*C));
    #pragma unroll
    for (int h = 0; h < H; h++) {
        float s = 0.f;
        #pragma unroll
        for (int d4 = 0; d4 < 8; d4++) {
            float4 kq = kvr[h*8 + d4];
            s += qs[h*D + 4*d4 + 0]*kq.x + qs[h*D + 4*d4 + 1]*kq.y
               + qs[h*D + 4*d4 + 2]*kq.z + qs[h*D + 4*d4 + 3]*kq.w;
        }
        g_qk[(((size_t)b*H + h)*T + t)*C + tid] = s * SCALE;
    }
}

// ---------------- kernel 3: attn = qk . feature^T  (96 x 8192 x 384 / batch) -
__global__ __launch_bounds__(256) void attn_gemm_kernel(const float* __restrict__ x) {
    int b  = blockIdx.y;
    int n0 = blockIdx.x * 128;
    int tid = threadIdx.x;
    int tx = tid & 15, ty = tid >> 4;      // 16x16 thread grid
    int kk = tid & 31, r  = tid >> 5;      // loader mapping

    __shared__ float As[32][97];
    __shared__ __align__(16) float Bs[32][130];   // row stride 520B (8B aligned)

    const float* qk   = g_qk + (size_t)b*HT*C;
    const float* feat = x + ((size_t)b*ROWS + T)*C;

    unsigned long long acc[6][4];
    #pragma unroll
    for (int i = 0; i < 6; i++)
        #pragma unroll
        for (int j = 0; j < 4; j++) acc[i][j] = 0ull;

    float pa[12], pb[16];
    #pragma unroll
    for (int i = 0; i < 12; i++) pa[i] = qk[(size_t)(r + 8*i)*C + kk];
    #pragma unroll
    for (int i = 0; i < 16; i++) pb[i] = feat[(size_t)(n0 + r + 8*i)*C + kk];

    for (int tile = 0; tile < 12; tile++) {
        #pragma unroll
        for (int i = 0; i < 12; i++) As[kk][r + 8*i] = pa[i];
        #pragma unroll
        for (int i = 0; i < 16; i++) Bs[kk][r + 8*i] = pb[i];
        __syncthreads();
        if (tile < 11) {
            int c1 = (tile + 1) * 32;
            #pragma unroll
            for (int i = 0; i < 12; i++) pa[i] = qk[(size_t)(r + 8*i)*C + c1 + kk];
            #pragma unroll
            for (int i = 0; i < 16; i++) pb[i] = feat[(size_t)(n0 + r + 8*i)*C + c1 + kk];
        }
        #pragma unroll
        for (int k2 = 0; k2 < 32; k2++) {
            unsigned long long a2[6], b2[4];
            #pragma unroll
            for (int i = 0; i < 6; i++) {
                float av = As[k2][ty + 16*i];
                a2[i] = pack2(av, av);
            }
            #pragma unroll
            for (int j = 0; j < 4; j++)
                b2[j] = *(const unsigned long long*)&Bs[k2][32*j + 2*tx];
            #pragma unroll
            for (int i = 0; i < 6; i++)
                #pragma unroll
                for (int j = 0; j < 4; j++) fma2(acc[i][j], a2[i], b2[j]);
        }
        __syncthreads();
    }

    float* outp = g_attn + (size_t)b*HT*NF;
    #pragma unroll
    for (int i = 0; i < 6; i++)
        #pragma unroll
        for (int j = 0; j < 4; j++) {
            float2 v;
            unpack2(acc[i][j], v.x, v.y);
            *(float2*)&outp[(size_t)(ty + 16*i)*NF + n0 + 32*j + 2*tx] = v;
        }
}

// ---------------- kernel 4: exact top-32 via 4-pass radix select --------------
__device__ __forceinline__ unsigned enc_key(unsigned b) {
    return (b & 0x80000000u) ? ~b : (b | 0x80000000u);
}
__device__ __forceinline__ float dec_key(unsigned u) {
    unsigned b = (u & 0x80000000u) ? (u ^ 0x80000000u) : ~u;
    return __uint_as_float(b);
}

__global__ __launch_bounds__(256) void topk_kernel() {
    int row = blockIdx.x;                  // b*HT + h*T + t
    int tid = threadIdx.x;                 // 256
    __shared__ unsigned keys[NF];          // 32KB
    __shared__ unsigned hist[256];
    __shared__ unsigned sscan[256];
    __shared__ unsigned sh_need, sh_prefix;
    __shared__ int cntG;
    __shared__ unsigned candK[TOPK];
    __shared__ int candI[TOPK];
    __shared__ int ri[256];
    __shared__ float outv[TOPK];
    __shared__ int outi[TOPK];

    const uint4* src = (const uint4*)(g_attn + (size_t)row*NF);
    for (int i = tid; i < NF/4; i += 256) {
        uint4 u = src[i];
        keys[4*i+0] = enc_key(u.x);
        keys[4*i+1] = enc_key(u.y);
        keys[4*i+2] = enc_key(u.z);
        keys[4*i+3] = enc_key(u.w);
    }
    if (tid == 0) { sh_need = TOPK; sh_prefix = 0; cntG = 0; }
    __syncthreads();

    #pragma unroll
    for (int pass = 0; pass < 4; pass++) {
        int shift = 24 - 8*pass;
        hist[tid] = 0;
        __syncthreads();
        unsigned pref  = sh_prefix;
        unsigned pmask = (pass == 0) ? 0u : (0xFFFFFFFFu << (shift + 8));
        for (int i = tid; i < NF; i += 256) {
            unsigned k = keys[i];
            if ((k & pmask) == pref) atomicAdd(&hist[(k >> shift) & 255], 1u);
        }
        __syncthreads();
        sscan[tid] = hist[tid];
        __syncthreads();
        for (int s = 1; s < 256; s <<= 1) {             // inclusive suffix sum
            unsigned v = (tid + s < 256) ? sscan[tid + s] : 0u;
            __syncthreads();
            sscan[tid] += v;
            __syncthreads();
        }
        unsigned need = sh_need;
        unsigned incl = sscan[tid];
        unsigned excl = incl - hist[tid];
        if (incl >= need && excl < need) {              // unique thread
            sh_prefix = pref | ((unsigned)tid << shift);
            sh_need   = need - excl;
        }
        __syncthreads();
    }
    unsigned V = sh_prefix;       // exact value of the 32nd-largest key
    int E = (int)sh_need;        // #ties (== V) needed, smallest indices first

    // collect keys strictly greater than V (exactly TOPK - E of them)
    for (int i = tid; i < NF; i += 256) {
        unsigned k = keys[i];
        if (k > V) { int p = atomicAdd(&cntG, 1); candK[p] = k; candI[p] = i; }
    }
    __syncthreads();
    int G = cntG;

    // ties: take the E smallest indices with key == V
    int last = -1;
    for (int e = 0; e < E; e++) {
        int best = NF;
        for (int i = tid; i < NF; i += 256)
            if (keys[i] == V && i > last && i < best) best = i;
        ri[tid] = best;
        __syncthreads();
        for (int s = 128; s > 0; s >>= 1) {
            if (tid < s) ri[tid] = min(ri[tid], ri[tid + s]);
            __syncthreads();
        }
        int widx = ri[0];
        if (tid == 0) { candK[G + e] = V; candI[G + e] = widx; }
        last = widx;
        __syncthreads();
    }

    // rank-sort the 32 candidates: value desc, index asc
    if (tid < 32) {
        unsigned k = candK[tid];
        int ix = candI[tid];
        unsigned long long ck =
            ((unsigned long long)k << 32) | (unsigned long long)(0xFFFFFFFFu - (unsigned)ix);
        int rank = 0;
        #pragma unroll
        for (int j = 0; j < 32; j++) {
            unsigned long long o = __shfl_sync(0xffffffffu, ck, j);
            rank += (o > ck);
        }
        outv[rank] = dec_key(k);
        outi[rank] = ix;
    }
    __syncwarp();
    if (tid < 32) {
        float m = outv[0];
        float e = expf(outv[tid] - m);
        float sum = e;
        #pragma unroll
        for (int o = 16; o > 0; o >>= 1) sum += __shfl_xor_sync(0xffffffffu, sum, o);
        g_w[row*TOPK + tid]   = e / sum;
        g_idx[row*TOPK + tid] = outi[tid];
    }
}

// ---------------- kernel 5a: fb[b,t,h,c] = sum_k w * feature[idx,c] ----------
__global__ __launch_bounds__(384) void token_gather_kernel(const float* __restrict__ x) {
    int t = blockIdx.x, h = blockIdx.y, b = blockIdx.z;
    int c = threadIdx.x;                   // 384
    __shared__ float wsh[TOPK];
    __shared__ int   ish[TOPK];
    int row = (b*H + h)*T + t;
    if (c < TOPK) { wsh[c] = g_w[row*TOPK + c]; ish[c] = g_idx[row*TOPK + c]; }
    __syncthreads();
    const float* feat = x + ((size_t)b*ROWS + T)*C;
    float a = 0.f;
    #pragma unroll
    for (int k = 0; k < TOPK; k++) a += wsh[k] * feat[(size_t)ish[k]*C + c];
    g_fb[(((size_t)b*T + t)*H + h)*C + c] = a;
}

// ---------------- kernel 5b: attn_token projection + token_out ---------------
__global__ __launch_bounds__(384) void token_out_kernel(const float* __restrict__ kv_w,
                                                        const float* __restrict__ experts_w,
                                                        float* __restrict__ out) {
    int b = blockIdx.y, t = blockIdx.x;
    int tid = threadIdx.x;                 // 384
    __shared__ float fb[H*C];              // 18KB
    __shared__ float at[C];

    const float* fbg = g_fb + ((size_t)b*T + t)*H*C;
    for (int i = tid; i < H*C; i += 384) fb[i] = fbg[i];
    __syncthreads();

    {
        int h = tid >> 5, d = tid & 31;
        float s = 0.f;
        const float* col = kv_w + C + h*D + d;      // v-half column
        #pragma unroll 8
        for (int c = 0; c < C; c++) s += fb[h*C + c] * col[(size_t)c*(2*C)];
        at[h*D + d] = s;
    }
    __syncthreads();
    {
        float o_acc = 0.f;
        const float* ew = experts_w + (size_t)t*C*C + tid;
        #pragma unroll 8
        for (int c = 0; c < C; c++) o_acc += at[c] * ew[(size_t)c*C];
        out[((size_t)b*ROWS + t)*C + tid] = o_acc;
    }
}

// ---------------- kernel 6: sparse feature_out scatter ------------------------
__global__ __launch_bounds__(384) void scatter_kernel(const float* __restrict__ x,
                                                      const float* __restrict__ experts_w,
                                                      float* __restrict__ out) {
    int t = blockIdx.x, h = blockIdx.y, b = blockIdx.z;
    int tid = threadIdx.x;                 // 384
    __shared__ float wsh[TOPK];
    __shared__ int   ish[TOPK];
    __shared__ float fsh[TOPK][D];

    int row = (b*H + h)*T + t;
    if (tid < TOPK) {
        wsh[tid] = g_w[row*TOPK + tid];
        ish[tid] = g_idx[row*TOPK + tid];
    }
    __syncthreads();

    const float* feat = x + ((size_t)b*ROWS + T)*C;
    for (int e = tid; e < TOPK*D; e += 384) {
        int k = e >> 5, d = e & 31;
        fsh[k][d] = feat[(size_t)ish[k]*C + h*D + d] * wsh[k];
    }
    __syncthreads();

    int o = tid;
    float ecol[D];
    const float* ew = experts_w + ((size_t)t*C + h*D)*C + o;
    #pragma unroll
    for (int d = 0; d < D; d++) ecol[d] = ew[(size_t)d*C];

    float* outb = out + ((size_t)b*ROWS + T)*C;
    for (int k = 0; k < TOPK; k++) {
        float s = 0.f;
        #pragma unroll
        for (int d = 0; d < D; d++) s += fsh[k][d] * ecol[d];
        atomicAdd(&outb[(size_t)ish[k]*C + o], s);
    }
}

// ---------------- launcher ----------------------------------------------------
extern "C" void kernel_launch(void* const* d_in, const int* in_sizes, int n_in,
                              void* d_out, int out_size) {
    const float* x = nullptr; const float* qs_w = nullptr;
    const float* kv_w = nullptr; const float* experts_w = nullptr;
    for (int i = 0; i < n_in; i++) {
        if (in_sizes[i] == B*ROWS*C)      x = (const float*)d_in[i];
        else if (in_sizes[i] == C*2*C)    kv_w = (const float*)d_in[i];
        else if (in_sizes[i] == T*C*C) {
            if (!qs_w) qs_w = (const float*)d_in[i];
            else       experts_w = (const float*)d_in[i];
        }
    }
    float* out = (float*)d_out;

    zero_out_kernel<<<1024, 256>>>((float4*)d_out, out_size / 4);
    q_kernel<<<dim3(3, T, B), 128>>>(x, qs_w);
    qk_kernel<<<dim3(T, B), 384>>>(kv_w);
    attn_gemm_kernel<<<dim3(NF/128, B), 256>>>(x);
    topk_kernel<<<B*HT, 256>>>();
    token_gather_kernel<<<dim3(T, H, B), 384>>>(x);
    token_out_kernel<<<dim3(T, B), 384>>>(kv_w, experts_w, out);
    scatter_kernel<<<dim3(T, H, B), 384>>>(x, experts_w, out);
}

// round 4
// speedup vs baseline: 1.4886x; 1.0696x over previous
#include <cuda_runtime.h>
#include <math.h>
#include <float.h>

#define B 4
#define T 8
#define NF 8192
#define C 384
#define H 12
#define TOPK 32
#define D 32
#define HT (H*T)        /* 96 */
#define ROWS (T+NF)     /* 8200 */
#define SCALE 0.17677669529663687f

typedef unsigned long long ull;

// ---------------- scratch (static device globals; no runtime alloc) ----------
__device__ float g_qk[B*HT*C];
__device__ float g_attn[(size_t)B*HT*NF];         // ~12.6MB
__device__ float g_w[B*HT*TOPK];
__device__ int   g_idx[B*HT*TOPK];
__device__ float g_fb[B*T*H*C];

// ---------------- f32x2 helpers (Blackwell packed FFMA) ----------------------
__device__ __forceinline__ ull pack2(float lo, float hi) {
    ull r;
    asm("mov.b64 %0, {%1, %2};" : "=l"(r) : "f"(lo), "f"(hi));
    return r;
}
__device__ __forceinline__ void unpack2(ull v, float& lo, float& hi) {
    asm("mov.b64 {%0, %1}, %2;" : "=f"(lo), "=f"(hi) : "l"(v));
}
__device__ __forceinline__ void fma2(ull& d, ull a, ull b) {
    asm("fma.rn.f32x2 %0, %1, %2, %0;" : "+l"(d) : "l"(a), "l"(b));
}

// ---------------- kernel 1: zero the output ----------------------------------
__global__ void zero_out_kernel(float4* __restrict__ out, int n4) {
    float4 z = make_float4(0.f, 0.f, 0.f, 0.f);
    for (int i = blockIdx.x * blockDim.x + threadIdx.x; i < n4;
         i += gridDim.x * blockDim.x)
        out[i] = z;
}

// ---------------- kernel 2: fused q projection + qk fold ---------------------
__global__ __launch_bounds__(384) void qqk_kernel(const float* __restrict__ x,
                                                  const float* __restrict__ qs_w,
                                                  const float* __restrict__ kv_w) {
    int b = blockIdx.y, t = blockIdx.x;
    int tid = threadIdx.x;                 // 384
    __shared__ float xs[C];
    __shared__ float qs[C];
    xs[tid] = x[((size_t)b*ROWS + t)*C + tid];
    __syncthreads();

    float acc = 0.f;
    const float* w = qs_w + (size_t)t*C*C + tid;
    #pragma unroll 16
    for (int c = 0; c < C; c++) acc += xs[c] * w[(size_t)c*C];
    qs[tid] = acc;
    __syncthreads();

    const float4* kvr = (const float4*)(kv_w + (size_t)tid*(2*C));
    #pragma unroll
    for (int h = 0; h < H; h++) {
        float s = 0.f;
        #pragma unroll
        for (int d4 = 0; d4 < 8; d4++) {
            float4 kq = kvr[h*8 + d4];
            s += qs[h*D + 4*d4 + 0]*kq.x + qs[h*D + 4*d4 + 1]*kq.y
               + qs[h*D + 4*d4 + 2]*kq.z + qs[h*D + 4*d4 + 3]*kq.w;
        }
        g_qk[(((size_t)b*H + h)*T + t)*C + tid] = s * SCALE;
    }
}

// ---------------- kernel 3: attn = qk . feature^T  (96 x 8192 x 384 / batch) -
// Dynamic smem, double-buffered; FFMA2 inner product; A stored [m][k].
struct GemmSmem {
    float As[2][96][34];     // [buf][m][k], row stride 34 floats (8B-aligned)
    float Bs[2][32][132];    // [buf][k][n], row stride 132 floats (16B-aligned)
};
#define GEMM_SMEM_BYTES sizeof(GemmSmem)

__global__ __launch_bounds__(256, 2) void attn_gemm_kernel(const float* __restrict__ x) {
    extern __shared__ __align__(16) char smem_raw[];
    GemmSmem& sm = *reinterpret_cast<GemmSmem*>(smem_raw);

    int b  = blockIdx.y;
    int n0 = blockIdx.x * 128;
    int tid = threadIdx.x;
    int tx = tid & 15, ty = tid >> 4;      // m = ty+16i, n = 2tx+32j
    int kk = tid & 31, r  = tid >> 5;      // loader: c = kk, row = r+8i

    const float* qk   = g_qk + (size_t)b*HT*C;
    const float* feat = x + ((size_t)b*ROWS + T)*C;

    ull acc[6][4];
    #pragma unroll
    for (int i = 0; i < 6; i++)
        #pragma unroll
        for (int j = 0; j < 4; j++) acc[i][j] = 0ull;

    float pa[12], pb[16];
    #pragma unroll
    for (int i = 0; i < 12; i++) pa[i] = qk[(size_t)(r + 8*i)*C + kk];
    #pragma unroll
    for (int i = 0; i < 16; i++) pb[i] = feat[(size_t)(n0 + r + 8*i)*C + kk];
    #pragma unroll
    for (int i = 0; i < 12; i++) sm.As[0][r + 8*i][kk] = pa[i];
    #pragma unroll
    for (int i = 0; i < 16; i++) sm.Bs[0][kk][r + 8*i] = pb[i];
    __syncthreads();

    #pragma unroll 1
    for (int tile = 0; tile < 12; tile++) {
        int cur = tile & 1;
        if (tile < 11) {
            int c1 = (tile + 1) * 32;
            #pragma unroll
            for (int i = 0; i < 12; i++) pa[i] = qk[(size_t)(r + 8*i)*C + c1 + kk];
            #pragma unroll
            for (int i = 0; i < 16; i++) pb[i] = feat[(size_t)(n0 + r + 8*i)*C + c1 + kk];
        }
        #pragma unroll
        for (int k = 0; k < 32; k += 2) {
            ull b0[4], b1[4];
            float2 a01[6];
            #pragma unroll
            for (int j = 0; j < 4; j++) {
                b0[j] = *(const ull*)&sm.Bs[cur][k    ][32*j + 2*tx];
                b1[j] = *(const ull*)&sm.Bs[cur][k + 1][32*j + 2*tx];
            }
            #pragma unroll
            for (int i = 0; i < 6; i++)
                a01[i] = *(const float2*)&sm.As[cur][ty + 16*i][k];
            #pragma unroll
            for (int i = 0; i < 6; i++) {
                ull au = pack2(a01[i].x, a01[i].x);
                ull av = pack2(a01[i].y, a01[i].y);
                #pragma unroll
                for (int j = 0; j < 4; j++) {
                    fma2(acc[i][j], au, b0[j]);
                    fma2(acc[i][j], av, b1[j]);
                }
            }
        }
        if (tile < 11) {
            int nxt = cur ^ 1;
            #pragma unroll
            for (int i = 0; i < 12; i++) sm.As[nxt][r + 8*i][kk] = pa[i];
            #pragma unroll
            for (int i = 0; i < 16; i++) sm.Bs[nxt][kk][r + 8*i] = pb[i];
            __syncthreads();
        }
    }

    float* outp = g_attn + (size_t)b*HT*NF;
    #pragma unroll
    for (int i = 0; i < 6; i++)
        #pragma unroll
        for (int j = 0; j < 4; j++) {
            float2 v;
            unpack2(acc[i][j], v.x, v.y);
            *(float2*)&outp[(size_t)(ty + 16*i)*NF + n0 + 32*j + 2*tx] = v;
        }
}

// ---------------- kernel 4: exact top-32 via 4-pass radix select --------------
__device__ __forceinline__ unsigned enc_key(unsigned b) {
    return (b & 0x80000000u) ? ~b : (b | 0x80000000u);
}
__device__ __forceinline__ float dec_key(unsigned u) {
    unsigned b = (u & 0x80000000u) ? (u ^ 0x80000000u) : ~u;
    return __uint_as_float(b);
}

__global__ __launch_bounds__(256) void topk_kernel() {
    int row = blockIdx.x;                  // b*HT + h*T + t
    int tid = threadIdx.x;                 // 256
    int lane = tid & 31, wp = tid >> 5;
    __shared__ unsigned keys[NF];          // 32KB
    __shared__ unsigned hist[256];
    __shared__ unsigned wsuf[8];
    __shared__ unsigned sh_need, sh_prefix;
    __shared__ int cntG;
    __shared__ unsigned candK[TOPK];
    __shared__ int candI[TOPK];
    __shared__ int ri[256];
    __shared__ float outv[TOPK];
    __shared__ int outi[TOPK];

    const uint4* src = (const uint4*)(g_attn + (size_t)row*NF);
    for (int i = tid; i < NF/4; i += 256) {
        uint4 u = src[i];
        keys[4*i+0] = enc_key(u.x);
        keys[4*i+1] = enc_key(u.y);
        keys[4*i+2] = enc_key(u.z);
        keys[4*i+3] = enc_key(u.w);
    }
    if (tid == 0) { sh_need = TOPK; sh_prefix = 0; cntG = 0; }
    __syncthreads();

    #pragma unroll
    for (int pass = 0; pass < 4; pass++) {
        int shift = 24 - 8*pass;
        hist[tid] = 0;
        __syncthreads();
        unsigned pref  = sh_prefix;
        unsigned pmask = (pass == 0) ? 0u : (0xFFFFFFFFu << (shift + 8));
        for (int i = tid; i < NF; i += 256) {
            unsigned k = keys[i];
            if ((k & pmask) == pref) atomicAdd(&hist[(k >> shift) & 255], 1u);
        }
        __syncthreads();

        // inclusive suffix sum over 256 bins: warp shuffle + 8-wide combine
        unsigned v = hist[tid];
        unsigned inc = v;
        #pragma unroll
        for (int s = 1; s < 32; s <<= 1) {
            unsigned tv = __shfl_down_sync(0xffffffffu, inc, s);
            if (lane + s < 32) inc += tv;
        }
        if (lane == 0) wsuf[wp] = inc;     // warp-total
        __syncthreads();
        if (tid < 8) {
            unsigned tv = wsuf[tid];
            #pragma unroll
            for (int s = 1; s < 8; s <<= 1) {
                unsigned t2 = __shfl_down_sync(0xffu, tv, s);
                if (tid + s < 8) tv += t2;
            }
            wsuf[tid] = tv;                // suffix over warp-totals
        }
        __syncthreads();
        unsigned incl = inc + (wp < 7 ? wsuf[wp + 1] : 0u);
        unsigned need = sh_need;
        unsigned excl = incl - v;
        if (incl >= need && excl < need) {              // unique thread
            sh_prefix = pref | ((unsigned)tid << shift);
            sh_need   = need - excl;
        }
        __syncthreads();
    }
    unsigned V = sh_prefix;       // exact value of the 32nd-largest key
    int E = (int)sh_need;         // #ties (== V) needed, smallest indices first

    // collect keys strictly greater than V (exactly TOPK - E of them)
    for (int i = tid; i < NF; i += 256) {
        unsigned k = keys[i];
        if (k > V) { int p = atomicAdd(&cntG, 1); candK[p] = k; candI[p] = i; }
    }
    __syncthreads();
    int G = cntG;

    // ties: take the E smallest indices with key == V
    int last = -1;
    for (int e = 0; e < E; e++) {
        int best = NF;
        for (int i = tid; i < NF; i += 256)
            if (keys[i] == V && i > last && i < best) best = i;
        ri[tid] = best;
        __syncthreads();
        for (int s = 128; s > 0; s >>= 1) {
            if (tid < s) ri[tid] = min(ri[tid], ri[tid + s]);
            __syncthreads();
        }
        int widx = ri[0];
        if (tid == 0) { candK[G + e] = V; candI[G + e] = widx; }
        last = widx;
        __syncthreads();
    }

    // rank-sort the 32 candidates: value desc, index asc
    if (tid < 32) {
        unsigned k = candK[tid];
        int ix = candI[tid];
        ull ck = ((ull)k << 32) | (ull)(0xFFFFFFFFu - (unsigned)ix);
        int rank = 0;
        #pragma unroll
        for (int j = 0; j < 32; j++) {
            ull o = __shfl_sync(0xffffffffu, ck, j);
            rank += (o > ck);
        }
        outv[rank] = dec_key(k);
        outi[rank] = ix;
    }
    __syncwarp();
    if (tid < 32) {
        float m = outv[0];
        float e = expf(outv[tid] - m);
        float sum = e;
        #pragma unroll
        for (int o = 16; o > 0; o >>= 1) sum += __shfl_xor_sync(0xffffffffu, sum, o);
        g_w[row*TOPK + tid]   = e / sum;
        g_idx[row*TOPK + tid] = outi[tid];
    }
}

// ---------------- kernel 5: fused gather (fb) + sparse feature scatter -------
__global__ __launch_bounds__(384) void gather_scatter_kernel(const float* __restrict__ x,
                                                             const float* __restrict__ experts_w,
                                                             float* __restrict__ out) {
    int t = blockIdx.x, h = blockIdx.y, b = blockIdx.z;
    int tid = threadIdx.x;                 // 384
    __shared__ float wsh[TOPK];
    __shared__ int   ish[TOPK];
    __shared__ float fsh[TOPK][D];

    int row = (b*H + h)*T + t;
    if (tid < TOPK) {
        wsh[tid] = g_w[row*TOPK + tid];
        ish[tid] = g_idx[row*TOPK + tid];
    }
    __syncthreads();

    const float* feat = x + ((size_t)b*ROWS + T)*C;
    int c = tid;
    int hD = h*D;
    bool mine = (c >= hD) && (c < hD + D);
    int d = c - hD;
    float a = 0.f;
    #pragma unroll
    for (int k = 0; k < TOPK; k++) {
        float v  = feat[(size_t)ish[k]*C + c];
        float wv = wsh[k] * v;
        a += wv;
        if (mine) fsh[k][d] = wv;
    }
    g_fb[(((size_t)b*T + t)*H + h)*C + c] = a;
    __syncthreads();

    // scatter: out[b, T+idx, o] += fsh[k,:] . experts_w[t, hD: , o]
    int o = tid;
    float ecol[D];
    const float* ew = experts_w + ((size_t)t*C + hD)*C + o;
    #pragma unroll
    for (int d2 = 0; d2 < D; d2++) ecol[d2] = ew[(size_t)d2*C];

    float* outb = out + ((size_t)b*ROWS + T)*C;
    for (int k = 0; k < TOPK; k++) {
        float s = 0.f;
        #pragma unroll
        for (int d2 = 0; d2 < D; d2++) s += fsh[k][d2] * ecol[d2];
        atomicAdd(&outb[(size_t)ish[k]*C + o], s);
    }
}

// ---------------- kernel 6: attn_token projection + token_out ----------------
__global__ __launch_bounds__(384) void token_out_kernel(const float* __restrict__ kv_w,
                                                        const float* __restrict__ experts_w,
                                                        float* __restrict__ out) {
    int b = blockIdx.y, t = blockIdx.x;
    int tid = threadIdx.x;                 // 384
    __shared__ float fb[H*C];              // 18KB
    __shared__ float at[C];

    const float* fbg = g_fb + ((size_t)b*T + t)*H*C;
    for (int i = tid; i < H*C; i += 384) fb[i] = fbg[i];
    __syncthreads();

    {
        int h = tid >> 5, d = tid & 31;
        float s = 0.f;
        const float* col = kv_w + C + h*D + d;      // v-half column
        #pragma unroll 8
        for (int c = 0; c < C; c++) s += fb[h*C + c] * col[(size_t)c*(2*C)];
        at[h*D + d] = s;
    }
    __syncthreads();
    {
        float o_acc = 0.f;
        const float* ew = experts_w + (size_t)t*C*C + tid;
        #pragma unroll 8
        for (int c = 0; c < C; c++) o_acc += at[c] * ew[(size_t)c*C];
        out[((size_t)b*ROWS + t)*C + tid] = o_acc;
    }
}

// ---------------- launcher ----------------------------------------------------
extern "C" void kernel_launch(void* const* d_in, const int* in_sizes, int n_in,
                              void* d_out, int out_size) {
    const float* x = nullptr; const float* qs_w = nullptr;
    const float* kv_w = nullptr; const float* experts_w = nullptr;
    for (int i = 0; i < n_in; i++) {
        if (in_sizes[i] == B*ROWS*C)      x = (const float*)d_in[i];
        else if (in_sizes[i] == C*2*C)    kv_w = (const float*)d_in[i];
        else if (in_sizes[i] == T*C*C) {
            if (!qs_w) qs_w = (const float*)d_in[i];
            else       experts_w = (const float*)d_in[i];
        }
    }
    float* out = (float*)d_out;

    // Opt-in to >48KB dynamic smem for the GEMM (attribute set, not a stream op).
    cudaFuncSetAttribute(attn_gemm_kernel,
                         cudaFuncAttributeMaxDynamicSharedMemorySize,
                         (int)GEMM_SMEM_BYTES);

    zero_out_kernel<<<1024, 256>>>((float4*)d_out, out_size / 4);
    qqk_kernel<<<dim3(T, B), 384>>>(x, qs_w, kv_w);
    attn_gemm_kernel<<<dim3(NF/128, B), 256, GEMM_SMEM_BYTES>>>(x);
    topk_kernel<<<B*HT, 256>>>();
    gather_scatter_kernel<<<dim3(T, H, B), 384>>>(x, experts_w, out);
    token_out_kernel<<<dim3(T, B), 384>>>(kv_w, experts_w, out);
}